// round 5
// baseline (speedup 1.0000x reference)
#include <cuda_runtime.h>
#include <cstdint>

#define B_     2
#define R_     512
#define C_     256
#define H0_    256
#define H1_    128
#define NBOX_  (B_ * R_)            // 1024
#define NCELLB_ 49
#define CG_    (C_ / 4)             // 64 float4 groups
#define THREADS_ 256

typedef unsigned long long u64;

struct Desc {                // 48 bytes
    int4 o;                  // byte offsets of 4 corners
    ulonglong2 wA;           // packed f32x2: {w00,w00}, {w01,w01}
    ulonglong2 wB;           // packed f32x2: {w10,w10}, {w11,w11}
};

__device__ __forceinline__ u64 fma2(u64 a, u64 b, u64 c) {
    u64 d;
    asm("fma.rn.f32x2 %0, %1, %2, %3;" : "=l"(d) : "l"(a), "l"(b), "l"(c));
    return d;
}
__device__ __forceinline__ u64 mul2(u64 a, u64 b) {
    u64 d;
    asm("mul.rn.f32x2 %0, %1, %2;" : "=l"(d) : "l"(a), "l"(b));
    return d;
}
__device__ __forceinline__ u64 bcast2(float w) {
    return (u64)__float_as_uint(w) * 0x100000001ULL;
}

__global__ __launch_bounds__(THREADS_) void roialign_kernel(
    const float* __restrict__ feat0,
    const float* __restrict__ feat1,
    const float* __restrict__ rois,
    float* __restrict__ out)
{
    __shared__ Desc cd[NCELLB_];
    __shared__ int s_lvl;

    int n = blockIdx.x;
    int t = threadIdx.x;

    if (t < NCELLB_) {
        const float* roi = rois + (size_t)n * 5;
        float y1 = roi[0], x1 = roi[1], y2 = roi[2], x2 = roi[3];
        bool lvl = ((y2 - y1) > 48.0f) || ((x2 - x1) > 48.0f);
        if (t == 0) s_lvl = lvl ? 1 : 0;
        int H = lvl ? H1_ : H0_;
        float Hm1 = (float)(H - 1);
        int b = n >> 9;

        const float inv = 1.0f / 1024.0f;
        float y1n = y1 * inv, x1n = x1 * inv, y2n = y2 * inv, x2n = x2 * inv;

        int py = t / 7;
        int px = t - py * 7;
        float ry = (float)py * (1.0f / 6.0f);
        float rx = (float)px * (1.0f / 6.0f);
        float ys = (y1n + ry * (y2n - y1n)) * Hm1;
        float xs = (x1n + rx * (x2n - x1n)) * Hm1;

        float validf = ((ys >= 0.0f) && (ys <= Hm1) && (xs >= 0.0f) && (xs <= Hm1))
                       ? 1.0f : 0.0f;

        float y0f = floorf(ys);
        float x0f = floorf(xs);
        float wy = ys - y0f;
        float wx = xs - x0f;
        // clamp coords (safe memory even when invalid)
        int y0 = (int)fminf(fmaxf(y0f, 0.0f), Hm1);
        int x0 = (int)fminf(fmaxf(x0f, 0.0f), Hm1);
        int yp = min(y0 + 1, H - 1);
        int xp = min(x0 + 1, H - 1);

        int rowB = H * (C_ * 4);               // bytes per feature row
        int baseB = (b * H + y0) * rowB;
        int basePB = (b * H + yp) * rowB;

        Desc d;
        d.o.x = baseB  + x0 * (C_ * 4);
        d.o.y = baseB  + xp * (C_ * 4);
        d.o.z = basePB + x0 * (C_ * 4);
        d.o.w = basePB + xp * (C_ * 4);

        float omwx = 1.0f - wx;
        float omwy = 1.0f - wy;
        d.wA.x = bcast2(omwx * omwy * validf);  // w00
        d.wA.y = bcast2(wx   * omwy * validf);  // w01
        d.wB.x = bcast2(omwx * wy   * validf);  // w10
        d.wB.y = bcast2(wx   * wy   * validf);  // w11
        cd[t] = d;
    }
    __syncthreads();

    const char* fbase = (const char*)(s_lvl ? feat1 : feat0) + (t & (CG_ - 1)) * 16;
    int cg   = t & (CG_ - 1);
    int lane = t >> 6;

    longlong2* outbase = (longlong2*)out + (size_t)n * NCELLB_ * (C_ / 4) + cg;

    #pragma unroll 4
    for (int cell = lane; cell < NCELLB_; cell += 4) {
        Desc d = cd[cell];
        ulonglong2 a = __ldg((const ulonglong2*)(fbase + d.o.x));
        ulonglong2 c = __ldg((const ulonglong2*)(fbase + d.o.y));
        ulonglong2 e = __ldg((const ulonglong2*)(fbase + d.o.z));
        ulonglong2 f = __ldg((const ulonglong2*)(fbase + d.o.w));

        ulonglong2 r;
        r.x = fma2(f.x, d.wB.y, fma2(e.x, d.wB.x, fma2(c.x, d.wA.y, mul2(a.x, d.wA.x))));
        r.y = fma2(f.y, d.wB.y, fma2(e.y, d.wB.x, fma2(c.y, d.wA.y, mul2(a.y, d.wA.x))));

        longlong2 rs;
        rs.x = (long long)r.x;
        rs.y = (long long)r.y;
        __stcs(outbase + cell * (C_ / 4), rs);
    }
}

extern "C" void kernel_launch(void* const* d_in, const int* in_sizes, int n_in,
                              void* d_out, int out_size)
{
    const float* feat0 = (const float*)d_in[0];
    const float* feat1 = (const float*)d_in[1];
    const float* rois  = (const float*)d_in[2];
    float* out = (float*)d_out;

    roialign_kernel<<<NBOX_, THREADS_>>>(feat0, feat1, rois, out);
}